// round 5
// baseline (speedup 1.0000x reference)
#include <cuda_runtime.h>
#include <math.h>

#define BATCH 2
#define TSEQ  4096
#define CDIM  768
#define HEADS 12
#define HDIM  64
#define MTOT  (BATCH * TSEQ)
#define KSTR  68   // smem row stride (floats) for attention tiles: 16B-aligned, avoids stride-64 bank conflicts

// Scratch (allocation-free rule: __device__ globals)
__device__ float g_q[MTOT * CDIM];
__device__ float g_k[MTOT * CDIM];
__device__ float g_v[MTOT * CDIM];
__device__ float g_att[MTOT * CDIM];

// ---------------------------------------------------------------------------
// Packed f32x2 helpers (sm_100+ PTX; 2x fp32 FMA throughput vs FFMA-3reg)
// ---------------------------------------------------------------------------
__device__ __forceinline__ unsigned long long pack_dup(float a) {
    unsigned long long r;
    unsigned int u = __float_as_uint(a);
    asm("mov.b64 %0, {%1, %1};" : "=l"(r) : "r"(u));
    return r;
}
__device__ __forceinline__ void fma2(unsigned long long& d,
                                     unsigned long long a,
                                     unsigned long long b) {
    asm("fma.rn.f32x2 %0, %1, %2, %0;" : "+l"(d) : "l"(a), "l"(b));
}

// ---------------------------------------------------------------------------
// C[m][n] = sum_k A[m][k] * W[n][k] + bias[n]   (torch Linear: x @ W.T + b)
// Block tile 128x128, BK=8, 256 threads, 8x8 microtile in f32x2 accumulators.
// Requires M%128==0, N%128==0, K%8==0 (holds: 8192, 768, 768).
// ---------------------------------------------------------------------------
__global__ __launch_bounds__(256, 2) void gemm_xwt(
    const float* __restrict__ A, const float* __restrict__ W,
    const float* __restrict__ bias, float* __restrict__ Cout,
    int M, int N, int K)
{
    __shared__ float As[8][128];   // [k][m]
    __shared__ float Ws[8][128];   // [k][n]
    const int tid = threadIdx.x;
    const int m0 = blockIdx.x * 128;
    const int n0 = blockIdx.y * 128;
    const int tx = tid & 15;        // col group
    const int ty = tid >> 4;        // row group
    const int lr = tid >> 1;        // load row 0..127
    const int lp = (tid & 1) * 4;   // k sub-offset 0 or 4

    unsigned long long acc[8][4];
#pragma unroll
    for (int i = 0; i < 8; i++)
#pragma unroll
        for (int j = 0; j < 4; j++) acc[i][j] = 0ULL;

    const float* Ap = A + (size_t)(m0 + lr) * K + lp;
    const float* Wp = W + (size_t)(n0 + lr) * K + lp;

    float4 av = *(const float4*)Ap;        // prefetch k-block 0
    float4 wv = *(const float4*)Wp;

    for (int kb = 0; kb < K; kb += 8) {
        __syncthreads();
        As[lp + 0][lr] = av.x; As[lp + 1][lr] = av.y;
        As[lp + 2][lr] = av.z; As[lp + 3][lr] = av.w;
        Ws[lp + 0][lr] = wv.x; Ws[lp + 1][lr] = wv.y;
        Ws[lp + 2][lr] = wv.z; Ws[lp + 3][lr] = wv.w;
        __syncthreads();
        if (kb + 8 < K) {                   // prefetch next k-block early
            av = *(const float4*)(Ap + kb + 8);
            wv = *(const float4*)(Wp + kb + 8);
        }
#pragma unroll
        for (int kk = 0; kk < 8; kk++) {
            const float4 a0 = *(const float4*)&As[kk][ty * 8];
            const float4 a1 = *(const float4*)&As[kk][ty * 8 + 4];
            const ulonglong2 b0 = *(const ulonglong2*)&Ws[kk][tx * 8];
            const ulonglong2 b1 = *(const ulonglong2*)&Ws[kk][tx * 8 + 4];
            const float afl[8] = {a0.x, a0.y, a0.z, a0.w, a1.x, a1.y, a1.z, a1.w};
#pragma unroll
            for (int i = 0; i < 8; i++) {
                const unsigned long long ap = pack_dup(afl[i]);
                fma2(acc[i][0], ap, b0.x);
                fma2(acc[i][1], ap, b0.y);
                fma2(acc[i][2], ap, b1.x);
                fma2(acc[i][3], ap, b1.y);
            }
        }
    }

    const float4 bb0 = *(const float4*)&bias[n0 + tx * 8];
    const float4 bb1 = *(const float4*)&bias[n0 + tx * 8 + 4];
#pragma unroll
    for (int i = 0; i < 8; i++) {
        const float2 p0 = *(const float2*)&acc[i][0];
        const float2 p1 = *(const float2*)&acc[i][1];
        const float2 p2 = *(const float2*)&acc[i][2];
        const float2 p3 = *(const float2*)&acc[i][3];
        float4 o0 = make_float4(p0.x + bb0.x, p0.y + bb0.y, p1.x + bb0.z, p1.y + bb0.w);
        float4 o1 = make_float4(p2.x + bb1.x, p2.y + bb1.y, p3.x + bb1.z, p3.y + bb1.w);
        float* Crow = Cout + (size_t)(m0 + ty * 8 + i) * N + n0 + tx * 8;
        *(float4*)Crow = o0;
        *(float4*)(Crow + 4) = o1;
    }
}

// ---------------------------------------------------------------------------
// Banded attention: |i - j| <= 16 (33 keys per query).
// One block = 32 queries x one head x one batch. Key tile = 64 rows
// [t0-16, t0+47]. Q,K,V read from plain [B*T, C] layout, output written to
// g_att in [B, T, H*D] layout (ready for the output projection GEMM).
// ---------------------------------------------------------------------------
__global__ __launch_bounds__(256) void attn_kernel()
{
    __shared__ float Kt[64][KSTR];
    __shared__ float Vt[64][KSTR];
    __shared__ float Qt[32][KSTR];
    __shared__ float S[32][36];

    const int tid = threadIdx.x;
    const int t0 = blockIdx.x * 32;
    const int h  = blockIdx.y;
    const int b  = blockIdx.z;
    const int kb = t0 - 16;                         // global index of key row 0
    const size_t base = (size_t)b * TSEQ * CDIM + (size_t)h * HDIM;

    // Stage K/V band tile (zero-fill out-of-range rows; they get masked anyway)
    for (int idx = tid; idx < 64 * 16; idx += 256) {
        const int row = idx >> 4;
        const int c4  = (idx & 15) << 2;
        const int tg  = kb + row;
        float4 kv = make_float4(0.f, 0.f, 0.f, 0.f);
        float4 vv = kv;
        if (tg >= 0 && tg < TSEQ) {
            const size_t off = base + (size_t)tg * CDIM + c4;
            kv = *(const float4*)(g_k + off);
            vv = *(const float4*)(g_v + off);
        }
        *(float4*)&Kt[row][c4] = kv;
        *(float4*)&Vt[row][c4] = vv;
    }
    // Stage Q tile
    for (int idx = tid; idx < 32 * 16; idx += 256) {
        const int row = idx >> 4;
        const int c4  = (idx & 15) << 2;
        *(float4*)&Qt[row][c4] =
            *(const float4*)(g_q + base + (size_t)(t0 + row) * CDIM + c4);
    }
    __syncthreads();

    // Scores: 8 threads per query, each covers offsets {ks, ks+8, ...} of 0..32
    const int q  = tid >> 3;
    const int ks = tid & 7;
    for (int off = ks; off <= 32; off += 8) {
        const int jj = q + off;            // row in Kt (0..63)
        const int tg = kb + jj;            // global key index
        float s = -INFINITY;
        if (tg >= 0 && tg < TSEQ) {
            float acc = 0.f;
#pragma unroll
            for (int d4 = 0; d4 < HDIM; d4 += 4) {
                const float4 qv = *(const float4*)&Qt[q][d4];
                const float4 kv = *(const float4*)&Kt[jj][d4];
                acc += qv.x * kv.x + qv.y * kv.y + qv.z * kv.z + qv.w * kv.w;
            }
            s = acc * 0.125f;              // D^-0.5 = 1/8
        }
        S[q][off] = s;
    }
    __syncthreads();

    // Softmax: one thread per query over its 33 scores
    if (tid < 32) {
        float mx = -INFINITY;
#pragma unroll
        for (int o = 0; o < 33; o++) mx = fmaxf(mx, S[tid][o]);
        float sum = 0.f;
#pragma unroll
        for (int o = 0; o < 33; o++) {
            const float e = __expf(S[tid][o] - mx);
            S[tid][o] = e;
            sum += e;
        }
        const float inv = 1.f / sum;
#pragma unroll
        for (int o = 0; o < 33; o++) S[tid][o] *= inv;
    }
    __syncthreads();

    // PV: 8 threads per query, each owns 8 output dims
    const int d0 = (tid & 7) << 3;
    float acc[8];
#pragma unroll
    for (int d = 0; d < 8; d++) acc[d] = 0.f;
    for (int off = 0; off <= 32; off++) {
        const float w = S[q][off];
        const float* vrow = &Vt[q + off][d0];
        const float4 v0 = *(const float4*)(vrow);
        const float4 v1 = *(const float4*)(vrow + 4);
        acc[0] += w * v0.x; acc[1] += w * v0.y; acc[2] += w * v0.z; acc[3] += w * v0.w;
        acc[4] += w * v1.x; acc[5] += w * v1.y; acc[6] += w * v1.z; acc[7] += w * v1.w;
    }
    float* outp = g_att + base + (size_t)(t0 + q) * CDIM + d0;
    *(float4*)outp       = make_float4(acc[0], acc[1], acc[2], acc[3]);
    *(float4*)(outp + 4) = make_float4(acc[4], acc[5], acc[6], acc[7]);
}

// ---------------------------------------------------------------------------
// Launch: 3 QKV GEMMs -> banded attention -> output projection GEMM
// ---------------------------------------------------------------------------
extern "C" void kernel_launch(void* const* d_in, const int* in_sizes, int n_in,
                              void* d_out, int out_size)
{
    const float* x  = (const float*)d_in[0];
    const float* Wq = (const float*)d_in[1];
    const float* bq = (const float*)d_in[2];
    const float* Wk = (const float*)d_in[3];
    const float* bk = (const float*)d_in[4];
    const float* Wv = (const float*)d_in[5];
    const float* bv = (const float*)d_in[6];
    const float* Wo = (const float*)d_in[7];
    const float* bo = (const float*)d_in[8];
    float* out = (float*)d_out;

    float *pq, *pk, *pv, *pa;
    cudaGetSymbolAddress((void**)&pq, g_q);
    cudaGetSymbolAddress((void**)&pk, g_k);
    cudaGetSymbolAddress((void**)&pv, g_v);
    cudaGetSymbolAddress((void**)&pa, g_att);

    dim3 gg(MTOT / 128, CDIM / 128);      // 64 x 6
    gemm_xwt<<<gg, 256>>>(x, Wq, bq, pq, MTOT, CDIM, CDIM);
    gemm_xwt<<<gg, 256>>>(x, Wk, bk, pk, MTOT, CDIM, CDIM);
    gemm_xwt<<<gg, 256>>>(x, Wv, bv, pv, MTOT, CDIM, CDIM);

    dim3 ga(TSEQ / 32, HEADS, BATCH);     // 128 x 12 x 2
    attn_kernel<<<ga, 256>>>();

    gemm_xwt<<<gg, 256>>>(pa, Wo, bo, out, MTOT, CDIM, CDIM);
}

// round 10
// speedup vs baseline: 2.2296x; 2.2296x over previous
#include <cuda_runtime.h>
#include <cuda_bf16.h>
#include <math.h>
#include <stdint.h>

#define BATCH 2
#define TSEQ  4096
#define CDIM  768
#define HEADS 12
#define HDIM  64
#define MTOT  (BATCH * TSEQ)
#define KSTR  68

// Scratch (allocation-free rule: __device__ globals)
__device__ float g_q[MTOT * CDIM];
__device__ float g_k[MTOT * CDIM];
__device__ float g_v[MTOT * CDIM];
__device__ float g_att[MTOT * CDIM];

// ---------------------------------------------------------------------------
// helpers
// ---------------------------------------------------------------------------
__device__ __forceinline__ uint32_t smem_u32(const void* p) {
    uint32_t a;
    asm("{ .reg .u64 t; cvta.to.shared.u64 t, %1; cvt.u32.u64 %0, t; }"
        : "=r"(a) : "l"(p));
    return a;
}
// pack (a -> low bf16, b -> high bf16)
__device__ __forceinline__ uint32_t cvt2(float a, float b) {
    uint32_t r;
    asm("cvt.rn.bf16x2.f32 %0, %1, %2;" : "=r"(r) : "f"(b), "f"(a));
    return r;
}
__device__ __forceinline__ float bflo(uint32_t h) { return __uint_as_float(h << 16); }
__device__ __forceinline__ float bfhi(uint32_t h) { return __uint_as_float(h & 0xFFFF0000u); }

__device__ __forceinline__ void ldsm4(uint32_t* r, uint32_t addr) {
    asm volatile("ldmatrix.sync.aligned.m8n8.x4.shared.b16 {%0,%1,%2,%3}, [%4];"
                 : "=r"(r[0]), "=r"(r[1]), "=r"(r[2]), "=r"(r[3]) : "r"(addr));
}
__device__ __forceinline__ void mma16816(float* d, const uint32_t* a,
                                         const uint32_t* b) {
    asm volatile(
        "mma.sync.aligned.m16n8k16.row.col.f32.bf16.bf16.f32 "
        "{%0,%1,%2,%3}, {%4,%5,%6,%7}, {%8,%9}, {%0,%1,%2,%3};"
        : "+f"(d[0]), "+f"(d[1]), "+f"(d[2]), "+f"(d[3])
        : "r"(a[0]), "r"(a[1]), "r"(a[2]), "r"(a[3]), "r"(b[0]), "r"(b[1]));
}

// ---------------------------------------------------------------------------
// HMMA GEMM: C[m][n] = sum_k A[m][k]*W[n][k] + bias[n]
// CTA 128x128, 8 warps (4 m x 2 n), warp tile 32x64, K-chunk 32.
// bf16 hi/lo split (3 MMA terms), fp32 accumulate.
// Smem tiles padded to 80B/row: ldmatrix phases are bank-conflict-free.
// ---------------------------------------------------------------------------
#define KC   32
#define NCH  (CDIM / KC)     // 24
#define SROW 80              // bytes per smem tile row (32 bf16 = 64B + 16B pad)

__global__ __launch_bounds__(256, 1) void gemm_mma(
    const float* __restrict__ A, const float* __restrict__ W,
    const float* __restrict__ bias, float* __restrict__ Cout)
{
    __shared__ __align__(16) uint8_t Ah[128 * SROW];
    __shared__ __align__(16) uint8_t Al[128 * SROW];
    __shared__ __align__(16) uint8_t Bh[128 * SROW];
    __shared__ __align__(16) uint8_t Bl[128 * SROW];

    const int tid  = threadIdx.x;
    const int lane = tid & 31;
    const int wid  = tid >> 5;
    const int mw   = wid & 3;          // warp m index (0..3) -> rows mw*32
    const int nw   = wid >> 2;         // warp n index (0..1) -> cols nw*64
    const int m0   = blockIdx.x * 128;
    const int n0   = blockIdx.y * 128;

    // staging mapping: row = tid/2 (0..127), k-offset = (tid&1)*16 floats
    const int lrow = tid >> 1;
    const int lk   = (tid & 1) * 16;
    const float* Ap = A + (size_t)(m0 + lrow) * CDIM + lk;
    const float* Wp = W + (size_t)(n0 + lrow) * CDIM + lk;
    const uint32_t st_off = (uint32_t)lrow * SROW + (uint32_t)lk * 2;  // bytes

    // ldmatrix lane addresses (bytes). A frag x4: row=R+(lane&15), col halves ks+(lane>>4)*8
    const uint32_t a_off =
        (uint32_t)(mw * 32 + (lane & 15)) * SROW + (uint32_t)(lane >> 4) * 16;
    // B frag x4 (2 n-tiles): row = N0 + (lane>>4)*8 + (lane&7), col halves ks + ((lane>>3)&1)*8
    const uint32_t b_off =
        (uint32_t)(nw * 64 + ((lane >> 4) << 3) + (lane & 7)) * SROW +
        (uint32_t)((lane >> 3) & 1) * 16;

    const uint32_t sAh = smem_u32(Ah) + a_off;
    const uint32_t sAl = smem_u32(Al) + a_off;
    const uint32_t sBh = smem_u32(Bh) + b_off;
    const uint32_t sBl = smem_u32(Bl) + b_off;

    float acc[2][8][4];
#pragma unroll
    for (int i = 0; i < 2; i++)
#pragma unroll
        for (int j = 0; j < 8; j++)
#pragma unroll
            for (int e = 0; e < 4; e++) acc[i][j][e] = 0.f;

    float4 ar[4], wr[4];
#pragma unroll
    for (int i = 0; i < 4; i++) {     // prologue: chunk 0 loads
        ar[i] = *(const float4*)(Ap + i * 4);
        wr[i] = *(const float4*)(Wp + i * 4);
    }

    for (int c = 0; c < NCH; c++) {
        // ---- convert fp32 -> bf16 hi/lo and store to smem ----
        uint4 ahv, alv, bhv, blv;
        {
            uint32_t h[8], l[8];
#pragma unroll
            for (int i = 0; i < 4; i++) {
                const float4 f = ar[i];
                h[2*i]   = cvt2(f.x, f.y);
                h[2*i+1] = cvt2(f.z, f.w);
                l[2*i]   = cvt2(f.x - bflo(h[2*i]),   f.y - bfhi(h[2*i]));
                l[2*i+1] = cvt2(f.z - bflo(h[2*i+1]), f.w - bfhi(h[2*i+1]));
            }
            ahv = make_uint4(h[0], h[1], h[2], h[3]);
            // pack remaining into second halves below
            alv = make_uint4(l[0], l[1], l[2], l[3]);
            // store first 8 floats worth; second 8 handled via h[4..7]
            *(uint4*)(Ah + st_off)      = ahv;
            *(uint4*)(Ah + st_off + 16) = make_uint4(h[4], h[5], h[6], h[7]);
            *(uint4*)(Al + st_off)      = alv;
            *(uint4*)(Al + st_off + 16) = make_uint4(l[4], l[5], l[6], l[7]);
#pragma unroll
            for (int i = 0; i < 4; i++) {
                const float4 f = wr[i];
                h[2*i]   = cvt2(f.x, f.y);
                h[2*i+1] = cvt2(f.z, f.w);
                l[2*i]   = cvt2(f.x - bflo(h[2*i]),   f.y - bfhi(h[2*i]));
                l[2*i+1] = cvt2(f.z - bflo(h[2*i+1]), f.w - bfhi(h[2*i+1]));
            }
            *(uint4*)(Bh + st_off)      = make_uint4(h[0], h[1], h[2], h[3]);
            *(uint4*)(Bh + st_off + 16) = make_uint4(h[4], h[5], h[6], h[7]);
            *(uint4*)(Bl + st_off)      = make_uint4(l[0], l[1], l[2], l[3]);
            *(uint4*)(Bl + st_off + 16) = make_uint4(l[4], l[5], l[6], l[7]);
        }
        __syncthreads();

        // ---- prefetch next chunk while MMAs run ----
        if (c + 1 < NCH) {
            const int ko = (c + 1) * KC;
#pragma unroll
            for (int i = 0; i < 4; i++) {
                ar[i] = *(const float4*)(Ap + ko + i * 4);
                wr[i] = *(const float4*)(Wp + ko + i * 4);
            }
        }

        // ---- MMAs over this chunk ----
#pragma unroll
        for (int ks = 0; ks < KC; ks += 16) {
            const uint32_t ks2 = (uint32_t)ks * 2;     // bytes
            uint32_t ahf[2][4], alf[2][4];
            ldsm4(ahf[0], sAh + ks2);
            ldsm4(ahf[1], sAh + 16 * SROW + ks2);
            ldsm4(alf[0], sAl + ks2);
            ldsm4(alf[1], sAl + 16 * SROW + ks2);
#pragma unroll
            for (int p = 0; p < 4; p++) {              // n-tile pairs
                uint32_t bhf[4], blf[4];
                ldsm4(bhf, sBh + (uint32_t)p * 16 * SROW + ks2);
                ldsm4(blf, sBl + (uint32_t)p * 16 * SROW + ks2);
#pragma unroll
                for (int mt = 0; mt < 2; mt++) {
#pragma unroll
                    for (int q = 0; q < 2; q++) {
                        float* d = acc[mt][p * 2 + q];
                        mma16816(d, ahf[mt], bhf + q * 2);
                        mma16816(d, ahf[mt], blf + q * 2);
                        mma16816(d, alf[mt], bhf + q * 2);
                    }
                }
            }
        }
        __syncthreads();
    }

    // ---- epilogue: add bias, store fp32 ----
    const int g  = lane >> 2;
    const int tg = lane & 3;
#pragma unroll
    for (int mt = 0; mt < 2; mt++) {
        const int row = m0 + mw * 32 + mt * 16 + g;
        float* r0 = Cout + (size_t)row * CDIM;
        float* r1 = Cout + (size_t)(row + 8) * CDIM;
#pragma unroll
        for (int nt = 0; nt < 8; nt++) {
            const int col = n0 + nw * 64 + nt * 8 + tg * 2;
            const float2 bb = *(const float2*)(bias + col);
            const float* d = acc[mt][nt];
            *(float2*)(r0 + col) = make_float2(d[0] + bb.x, d[1] + bb.y);
            *(float2*)(r1 + col) = make_float2(d[2] + bb.x, d[3] + bb.y);
        }
    }
}

// ---------------------------------------------------------------------------
// Banded attention: |i - j| <= 16 (33 keys per query).
// 512 threads / 32 queries; 16 threads per query, 4 dims each in PV
// (conflict-free LDS phases).
// ---------------------------------------------------------------------------
__global__ __launch_bounds__(512) void attn_kernel()
{
    __shared__ float Kt[64][KSTR];
    __shared__ float Vt[64][KSTR];
    __shared__ float Qt[32][KSTR];
    __shared__ float S[32][36];

    const int tid = threadIdx.x;
    const int t0 = blockIdx.x * 32;
    const int h  = blockIdx.y;
    const int b  = blockIdx.z;
    const int kb = t0 - 16;
    const size_t base = (size_t)b * TSEQ * CDIM + (size_t)h * HDIM;

    for (int idx = tid; idx < 64 * 16; idx += 512) {
        const int row = idx >> 4;
        const int c4  = (idx & 15) << 2;
        const int tg  = kb + row;
        float4 kv = make_float4(0.f, 0.f, 0.f, 0.f);
        float4 vv = kv;
        if (tg >= 0 && tg < TSEQ) {
            const size_t off = base + (size_t)tg * CDIM + c4;
            kv = *(const float4*)(g_k + off);
            vv = *(const float4*)(g_v + off);
        }
        *(float4*)&Kt[row][c4] = kv;
        *(float4*)&Vt[row][c4] = vv;
    }
    for (int idx = tid; idx < 32 * 16; idx += 512) {
        const int row = idx >> 4;
        const int c4  = (idx & 15) << 2;
        *(float4*)&Qt[row][c4] =
            *(const float4*)(g_q + base + (size_t)(t0 + row) * CDIM + c4);
    }
    __syncthreads();

    // Scores: 16 threads per query, offsets {ks, ks+16, (ks==0: 32)}
    const int q  = tid >> 4;
    const int ks = tid & 15;
    for (int off = ks; off <= 32; off += 16) {
        const int jj = q + off;
        const int tg = kb + jj;
        float s = -INFINITY;
        if (tg >= 0 && tg < TSEQ) {
            float acc = 0.f;
#pragma unroll
            for (int d4 = 0; d4 < HDIM; d4 += 4) {
                const float4 qv = *(const float4*)&Qt[q][d4];
                const float4 kv = *(const float4*)&Kt[jj][d4];
                acc += qv.x * kv.x + qv.y * kv.y + qv.z * kv.z + qv.w * kv.w;
            }
            s = acc * 0.125f;
        }
        S[q][off] = s;
    }
    __syncthreads();

    if (tid < 32) {
        float mx = -INFINITY;
#pragma unroll
        for (int o = 0; o < 33; o++) mx = fmaxf(mx, S[tid][o]);
        float sum = 0.f;
#pragma unroll
        for (int o = 0; o < 33; o++) {
            const float e = __expf(S[tid][o] - mx);
            S[tid][o] = e;
            sum += e;
        }
        const float inv = 1.f / sum;
#pragma unroll
        for (int o = 0; o < 33; o++) S[tid][o] *= inv;
    }
    __syncthreads();

    // PV: 16 threads per query, 4 dims each
    const int d0 = (tid & 15) << 2;
    float a0 = 0.f, a1 = 0.f, a2 = 0.f, a3 = 0.f;
    for (int off = 0; off <= 32; off++) {
        const float w = S[q][off];
        const float4 v = *(const float4*)&Vt[q + off][d0];
        a0 += w * v.x; a1 += w * v.y; a2 += w * v.z; a3 += w * v.w;
    }
    *(float4*)(g_att + base + (size_t)(t0 + q) * CDIM + d0) =
        make_float4(a0, a1, a2, a3);
}

// ---------------------------------------------------------------------------
// Launch
// ---------------------------------------------------------------------------
extern "C" void kernel_launch(void* const* d_in, const int* in_sizes, int n_in,
                              void* d_out, int out_size)
{
    const float* x  = (const float*)d_in[0];
    const float* Wq = (const float*)d_in[1];
    const float* bq = (const float*)d_in[2];
    const float* Wk = (const float*)d_in[3];
    const float* bk = (const float*)d_in[4];
    const float* Wv = (const float*)d_in[5];
    const float* bv = (const float*)d_in[6];
    const float* Wo = (const float*)d_in[7];
    const float* bo = (const float*)d_in[8];
    float* out = (float*)d_out;

    float *pq, *pk, *pv, *pa;
    cudaGetSymbolAddress((void**)&pq, g_q);
    cudaGetSymbolAddress((void**)&pk, g_k);
    cudaGetSymbolAddress((void**)&pv, g_v);
    cudaGetSymbolAddress((void**)&pa, g_att);

    dim3 gg(MTOT / 128, CDIM / 128);      // 64 x 6
    gemm_mma<<<gg, 256>>>(x, Wq, bq, pq);
    gemm_mma<<<gg, 256>>>(x, Wk, bk, pk);
    gemm_mma<<<gg, 256>>>(x, Wv, bv, pv);

    dim3 ga(TSEQ / 32, HEADS, BATCH);     // 128 x 12 x 2
    attn_kernel<<<ga, 512>>>();

    gemm_mma<<<gg, 256>>>(pa, Wo, bo, out);
}